// round 1
// baseline (speedup 1.0000x reference)
#include <cuda_runtime.h>

// OldNoiseConv: y[o,p] = b[o] + sum_i W[o,i] * x[i,p] * (1 + 0.1*eps[p,o,i])
// x  : [2,64,16,1024] fp32 viewed as xf[64][32768]   (8 MB)
// W  : [64,64] fp32
// b  : [64] fp32
// eps: [32768,64,64] fp32  (512 MB, read-once -> HBM-bound)
// out: [64][32768] fp32    (row-major flatten == reference reshape)

#define P_TOT   32768
#define NCH     64          // CI == CO == 64
#define NB      1024        // blocks
#define PPB     32          // points per block
#define NTHREADS 256
#define PPW     4           // points per warp (8 warps/block)
#define WPAD    68          // padded row stride (floats) for conflict-free LDS.128

__global__ __launch_bounds__(NTHREADS)
void noise_conv_kernel(const float* __restrict__ x,
                       const float* __restrict__ W,
                       const float* __restrict__ b,
                       const float* __restrict__ eps,
                       float* __restrict__ out)
{
    __shared__ float Ws[NCH][WPAD];       // W rows, padded
    __shared__ float xs[PPB][WPAD];       // x[:,p] for this block's points, pt-major
    __shared__ float ys[NCH][PPB + 1];    // output staging, padded
    __shared__ float bs[NCH];

    const int t  = threadIdx.x;
    const int p0 = blockIdx.x * PPB;

    // ---- stage W (4096 floats, coalesced) ----
    #pragma unroll
    for (int r = 0; r < 16; r++) {
        int idx = r * NTHREADS + t;
        Ws[idx >> 6][idx & 63] = W[idx];
    }
    if (t < NCH) bs[t] = b[t];

    // ---- stage x: xs[c][i] = xf[i, p0+c]  (2048 floats, coalesced in c) ----
    #pragma unroll
    for (int r = 0; r < 8; r++) {
        int idx = r * NTHREADS + t;
        int i = idx >> 5;          // channel 0..63
        int c = idx & 31;          // point offset 0..31
        xs[c][i] = x[(size_t)i * P_TOT + p0 + c];
    }
    __syncthreads();

    // ---- main loop: warp processes PPW points; per pass, 4 eps rows (o),
    //      8 lanes per row, each lane reads 2 contiguous float4 (32B).
    //      LDG.128 per instruction covers 4 full 128B lines -> perfect coalescing.
    const int w  = t >> 5;
    const int l  = t & 31;
    const int r4 = l >> 3;   // which of the 4 rows in this pass
    const int c8 = l & 7;    // float4 column within row half

    for (int pl = 0; pl < PPW; pl++) {
        const int pt = w * PPW + pl;
        const int p  = p0 + pt;

        const float4* xr  = reinterpret_cast<const float4*>(&xs[pt][0]);
        const float4  xv0 = xr[c8];
        const float4  xv1 = xr[8 + c8];

        const float4* ep = reinterpret_cast<const float4*>(eps) + (size_t)p * 1024;

        #pragma unroll 4
        for (int pass = 0; pass < 16; pass++) {
            const int o = (pass << 2) + r4;
            // eps row o of point p: this lane's 8 floats (cols 4*c8.. and 4*(c8+8)..)
            const float4 e0 = __ldcs(ep + (o << 4) + c8);
            const float4 e1 = __ldcs(ep + (o << 4) + 8 + c8);
            const float4* wr = reinterpret_cast<const float4*>(&Ws[o][0]);
            const float4 w0 = wr[c8];
            const float4 w1 = wr[8 + c8];

            float s;
            s = (w0.x * xv0.x) * fmaf(e0.x, 0.1f, 1.0f);
            s = fmaf(w0.y * xv0.y, fmaf(e0.y, 0.1f, 1.0f), s);
            s = fmaf(w0.z * xv0.z, fmaf(e0.z, 0.1f, 1.0f), s);
            s = fmaf(w0.w * xv0.w, fmaf(e0.w, 0.1f, 1.0f), s);
            s = fmaf(w1.x * xv1.x, fmaf(e1.x, 0.1f, 1.0f), s);
            s = fmaf(w1.y * xv1.y, fmaf(e1.y, 0.1f, 1.0f), s);
            s = fmaf(w1.z * xv1.z, fmaf(e1.z, 0.1f, 1.0f), s);
            s = fmaf(w1.w * xv1.w, fmaf(e1.w, 0.1f, 1.0f), s);

            // reduce the 8 lanes of each row (all 4 rows reduced simultaneously)
            s += __shfl_xor_sync(0xffffffffu, s, 1);
            s += __shfl_xor_sync(0xffffffffu, s, 2);
            s += __shfl_xor_sync(0xffffffffu, s, 4);

            if (c8 == 0) ys[o][pt] = s;
        }
    }
    __syncthreads();

    // ---- flush: fully coalesced stores (128B per warp), add bias ----
    #pragma unroll
    for (int rr = 0; rr < 8; rr++) {
        int idx = rr * NTHREADS + t;
        int o = idx >> 5;
        int c = idx & 31;
        out[(size_t)o * P_TOT + p0 + c] = ys[o][c] + bs[o];
    }
}

extern "C" void kernel_launch(void* const* d_in, const int* in_sizes, int n_in,
                              void* d_out, int out_size)
{
    const float* x   = (const float*)d_in[0];
    const float* W   = (const float*)d_in[1];
    const float* b   = (const float*)d_in[2];
    const float* eps = (const float*)d_in[3];
    float* out = (float*)d_out;
    (void)in_sizes; (void)n_in; (void)out_size;

    noise_conv_kernel<<<NB, NTHREADS>>>(x, W, b, eps, out);
}

// round 2
// speedup vs baseline: 1.1586x; 1.1586x over previous
#include <cuda_runtime.h>

// OldNoiseConv: y[o,p] = b[o] + sum_i W[o,i] * x[i,p] * (1 + 0.1*eps[p,o,i])
// eps [32768,64,64] fp32 = 512MB read-once -> HBM-bound.
// R2: distance-2 register prefetch pipeline on eps so every warp keeps LDGs
// outstanding through the FFMA+SHFL compute tail (fixes 0.58 load duty cycle).

#define P_TOT    32768
#define NCH      64
#define NB       1024
#define PPB      32
#define NTHREADS 256
#define PPW      4
#define WPAD     68

__global__ __launch_bounds__(NTHREADS, 4)
void noise_conv_kernel(const float* __restrict__ x,
                       const float* __restrict__ W,
                       const float* __restrict__ b,
                       const float* __restrict__ eps,
                       float* __restrict__ out)
{
    __shared__ float Ws[NCH][WPAD];
    __shared__ float xs[PPB][WPAD];
    __shared__ float ys[NCH][PPB + 1];
    __shared__ float bs[NCH];

    const int t  = threadIdx.x;
    const int p0 = blockIdx.x * PPB;

    // stage W (coalesced)
    #pragma unroll
    for (int r = 0; r < 16; r++) {
        int idx = r * NTHREADS + t;
        Ws[idx >> 6][idx & 63] = W[idx];
    }
    if (t < NCH) bs[t] = b[t];

    // stage x: xs[c][i] = xf[i, p0+c]
    #pragma unroll
    for (int r = 0; r < 8; r++) {
        int idx = r * NTHREADS + t;
        int i = idx >> 5;
        int c = idx & 31;
        xs[c][i] = x[(size_t)i * P_TOT + p0 + c];
    }
    __syncthreads();

    const int w  = t >> 5;
    const int l  = t & 31;
    const int r4 = l >> 3;   // row within 4-row pass group
    const int c8 = l & 7;    // float4 column within row half

    for (int pl = 0; pl < PPW; pl++) {
        const int pt = w * PPW + pl;
        const int p  = p0 + pt;

        const float4* xr  = reinterpret_cast<const float4*>(&xs[pt][0]);
        const float4  xv0 = xr[c8];
        const float4  xv1 = xr[8 + c8];

        const float4* ep = reinterpret_cast<const float4*>(eps) + (size_t)p * 1024;

        // prefetch passes 0 and 1 (distance-2 pipeline)
        float4 a0 = __ldcs(ep + ((0 * 4 + r4) << 4) + c8);
        float4 a1 = __ldcs(ep + ((0 * 4 + r4) << 4) + 8 + c8);
        float4 b0 = __ldcs(ep + ((1 * 4 + r4) << 4) + c8);
        float4 b1 = __ldcs(ep + ((1 * 4 + r4) << 4) + 8 + c8);

        #pragma unroll
        for (int pass = 0; pass < 16; pass++) {
            const int o = (pass << 2) + r4;

            float4 n0, n1;
            if (pass < 14) {
                const int off = (((pass + 2) << 2) + r4) << 4;
                n0 = __ldcs(ep + off + c8);
                n1 = __ldcs(ep + off + 8 + c8);
            }

            const float4* wr = reinterpret_cast<const float4*>(&Ws[o][0]);
            const float4 w0 = wr[c8];
            const float4 w1 = wr[8 + c8];

            // two independent accumulator chains (depth 4 instead of 8)
            float s0 = (w0.x * xv0.x) * fmaf(a0.x, 0.1f, 1.0f);
            float s1 = (w0.y * xv0.y) * fmaf(a0.y, 0.1f, 1.0f);
            s0 = fmaf(w0.z * xv0.z, fmaf(a0.z, 0.1f, 1.0f), s0);
            s1 = fmaf(w0.w * xv0.w, fmaf(a0.w, 0.1f, 1.0f), s1);
            s0 = fmaf(w1.x * xv1.x, fmaf(a1.x, 0.1f, 1.0f), s0);
            s1 = fmaf(w1.y * xv1.y, fmaf(a1.y, 0.1f, 1.0f), s1);
            s0 = fmaf(w1.z * xv1.z, fmaf(a1.z, 0.1f, 1.0f), s0);
            s1 = fmaf(w1.w * xv1.w, fmaf(a1.w, 0.1f, 1.0f), s1);
            float s = s0 + s1;

            s += __shfl_xor_sync(0xffffffffu, s, 1);
            s += __shfl_xor_sync(0xffffffffu, s, 2);
            s += __shfl_xor_sync(0xffffffffu, s, 4);

            if (c8 == 0) ys[o][pt] = s;

            // shift pipeline registers
            a0 = b0; a1 = b1;
            b0 = n0; b1 = n1;
        }
    }
    __syncthreads();

    // coalesced flush + bias
    #pragma unroll
    for (int rr = 0; rr < 8; rr++) {
        int idx = rr * NTHREADS + t;
        int o = idx >> 5;
        int c = idx & 31;
        out[(size_t)o * P_TOT + p0 + c] = ys[o][c] + bs[o];
    }
}

extern "C" void kernel_launch(void* const* d_in, const int* in_sizes, int n_in,
                              void* d_out, int out_size)
{
    const float* x   = (const float*)d_in[0];
    const float* W   = (const float*)d_in[1];
    const float* b   = (const float*)d_in[2];
    const float* eps = (const float*)d_in[3];
    float* out = (float*)d_out;
    (void)in_sizes; (void)n_in; (void)out_size;

    noise_conv_kernel<<<NB, NTHREADS>>>(x, W, b, eps, out);
}

// round 3
// speedup vs baseline: 1.2870x; 1.1109x over previous
#include <cuda_runtime.h>

// OldNoiseConv: y[o,p] = b[o] + sum_i W[o,i] * x[i,p] * (1 + 0.1*eps[p,o,i])
// eps [32768,64,64] fp32 = 512MB read-once -> HBM-bound (floor ~76us).
// R3: small blocks (8 points, grid 4096 -> 6.92 waves, 92%-full last wave),
// depth-3 eps prefetch issued BEFORE staging/sync so DRAM never idles at
// block start. One point per warp.

#define P_TOT    32768
#define NCH      64
#define PPB      8
#define NB       (P_TOT / PPB)     // 4096
#define NTHREADS 256
#define WPAD     68                // padded row stride (floats), 272B = 16B aligned

__global__ __launch_bounds__(NTHREADS, 4)
void noise_conv_kernel(const float* __restrict__ x,
                       const float* __restrict__ W,
                       const float* __restrict__ b,
                       const float* __restrict__ eps,
                       float* __restrict__ out)
{
    __shared__ float Ws[NCH][WPAD];
    __shared__ float xs[PPB][WPAD];
    __shared__ float ys[NCH][PPB + 1];
    __shared__ float bs[NCH];

    const int t  = threadIdx.x;
    const int w  = t >> 5;
    const int l  = t & 31;
    const int r4 = l >> 3;    // which of 4 output rows this pass
    const int c8 = l & 7;     // float4 column within row half
    const int p0 = blockIdx.x * PPB;
    const int p  = p0 + w;    // this warp's point

    // ---- eps prefetch FIRST (independent of smem): DRAM streams from cycle 0
    const float4* ep = reinterpret_cast<const float4*>(eps) + (size_t)p * 1024;
    float4 A0 = __ldcs(ep + ((0 * 4 + r4) << 4) + c8);
    float4 A1 = __ldcs(ep + ((0 * 4 + r4) << 4) + 8 + c8);
    float4 B0 = __ldcs(ep + ((1 * 4 + r4) << 4) + c8);
    float4 B1 = __ldcs(ep + ((1 * 4 + r4) << 4) + 8 + c8);
    float4 C0 = __ldcs(ep + ((2 * 4 + r4) << 4) + c8);
    float4 C1 = __ldcs(ep + ((2 * 4 + r4) << 4) + 8 + c8);

    // ---- stage W via float4 (1024 float4 = 4 per thread)
    {
        const float4* Wv = reinterpret_cast<const float4*>(W);
        #pragma unroll
        for (int r = 0; r < 4; r++) {
            int idx = r * NTHREADS + t;          // 0..1023
            int row = idx >> 4;
            int c4  = idx & 15;
            *reinterpret_cast<float4*>(&Ws[row][c4 << 2]) = Wv[idx];
        }
    }
    if (t < NCH) bs[t] = b[t];

    // ---- stage x: xs[c][i] = xf[i, p0+c]  (512 floats)
    #pragma unroll
    for (int r = 0; r < 2; r++) {
        int idx = r * NTHREADS + t;
        int i = idx >> 3;
        int c = idx & 7;
        xs[c][i] = x[(size_t)i * P_TOT + p0 + c];
    }
    __syncthreads();

    const float4* xr  = reinterpret_cast<const float4*>(&xs[w][0]);
    const float4  xv0 = xr[c8];
    const float4  xv1 = xr[8 + c8];

    // ---- 16 passes, depth-3 register pipeline on eps
    #pragma unroll
    for (int pass = 0; pass < 16; pass++) {
        const int o = (pass << 2) + r4;

        float4 N0, N1;
        if (pass < 13) {
            const int off = (((pass + 3) << 2) + r4) << 4;
            N0 = __ldcs(ep + off + c8);
            N1 = __ldcs(ep + off + 8 + c8);
        }

        const float4* wr = reinterpret_cast<const float4*>(&Ws[o][0]);
        const float4 w0 = wr[c8];
        const float4 w1 = wr[8 + c8];

        float s0 = (w0.x * xv0.x) * fmaf(A0.x, 0.1f, 1.0f);
        float s1 = (w0.y * xv0.y) * fmaf(A0.y, 0.1f, 1.0f);
        s0 = fmaf(w0.z * xv0.z, fmaf(A0.z, 0.1f, 1.0f), s0);
        s1 = fmaf(w0.w * xv0.w, fmaf(A0.w, 0.1f, 1.0f), s1);
        s0 = fmaf(w1.x * xv1.x, fmaf(A1.x, 0.1f, 1.0f), s0);
        s1 = fmaf(w1.y * xv1.y, fmaf(A1.y, 0.1f, 1.0f), s1);
        s0 = fmaf(w1.z * xv1.z, fmaf(A1.z, 0.1f, 1.0f), s0);
        s1 = fmaf(w1.w * xv1.w, fmaf(A1.w, 0.1f, 1.0f), s1);
        float s = s0 + s1;

        s += __shfl_xor_sync(0xffffffffu, s, 1);
        s += __shfl_xor_sync(0xffffffffu, s, 2);
        s += __shfl_xor_sync(0xffffffffu, s, 4);

        if (c8 == 0) ys[o][w] = s;

        A0 = B0; A1 = B1;
        B0 = C0; B1 = C1;
        C0 = N0; C1 = N1;
    }
    __syncthreads();

    // ---- flush (512 floats), add bias
    #pragma unroll
    for (int r = 0; r < 2; r++) {
        int idx = r * NTHREADS + t;
        int o = idx >> 3;
        int c = idx & 7;
        out[(size_t)o * P_TOT + p0 + c] = ys[o][c] + bs[o];
    }
}

extern "C" void kernel_launch(void* const* d_in, const int* in_sizes, int n_in,
                              void* d_out, int out_size)
{
    const float* x   = (const float*)d_in[0];
    const float* W   = (const float*)d_in[1];
    const float* b   = (const float*)d_in[2];
    const float* eps = (const float*)d_in[3];
    float* out = (float*)d_out;
    (void)in_sizes; (void)n_in; (void)out_size;

    noise_conv_kernel<<<NB, NTHREADS>>>(x, W, b, eps, out);
}